// round 9
// baseline (speedup 1.0000x reference)
#include <cuda_runtime.h>
#include <math.h>
#include <stdint.h>

// ---------------------------------------------------------------------------
// Problem constants
//   feat[1,128,128,128] lr_guide[1,128,128,128] hr_guide[1,128,256,256]
//   W1[386,256] b1[256] W2[256,128] b2[128] W3[128,32] b3[32]
//   out [1,32,256,256] fp32
// ---------------------------------------------------------------------------
#define H_LR 128
#define W_LR 128
#define NPIX_LR (H_LR * W_LR)        // 16384
#define H_HR 256
#define W_HR 256
#define NPTS (H_HR * W_HR)           // 65536

typedef unsigned long long ull;

// ---- packed fp32x2 helpers (FFMA2 path) -----------------------------------
__device__ __forceinline__ ull pack2(float lo, float hi) {
    ull r; asm("mov.b64 %0, {%1,%2};" : "=l"(r) : "f"(lo), "f"(hi)); return r;
}
__device__ __forceinline__ ull fma2(ull a, ull b, ull c) {
    ull d; asm("fma.rn.f32x2 %0, %1, %2, %3;" : "=l"(d) : "l"(a), "l"(b), "l"(c));
    return d;
}
__device__ __forceinline__ float2 unpack2(ull v) {
    float2 f; asm("mov.b64 {%0,%1}, %2;" : "=f"(f.x), "=f"(f.y) : "l"(v)); return f;
}

// ---- cp.async helpers -----------------------------------------------------
__device__ __forceinline__ uint32_t smem_u32(const void* p) {
    uint32_t a;
    asm("{ .reg .u64 t; cvta.to.shared.u64 t, %1; cvt.u32.u64 %0, t; }"
        : "=r"(a) : "l"(p));
    return a;
}
__device__ __forceinline__ void cp16(uint32_t dst, const void* src) {
    asm volatile("cp.async.ca.shared.global [%0], [%1], 16;"
                 :: "r"(dst), "l"(src));
}
#define CP_COMMIT() asm volatile("cp.async.commit_group;" ::: "memory")
#define CP_WAIT(n)  asm volatile("cp.async.wait_group %0;" :: "n"(n) : "memory")

// 16B-unit XOR swizzle: distinct bank-quads within an 8-thread LDS phase
__device__ __forceinline__ int swz(int u) { return u ^ ((u >> 3) & 7); }

// Scratch (device global: allocation-free per harness rules)
__device__ float g_h1f[NPIX_LR * 256];   // layer1 featc part per LR pixel (16 MB)

// ---------------------------------------------------------------------------
// K1 GEMM: h1f[p][n] = sum_c featc[c][p] * W1[c*256+n]
//   featc[c] = (c<128) ? lr_guide[c] : feat[c-128]
// BM=128, BN=128, BK=16, 256 threads, 8x8/thread (f32x2),
// 3-stage cp.async pipeline, XOR-swizzled smem units.
// ---------------------------------------------------------------------------
__global__ __launch_bounds__(256, 2) void gemm_l1f(
    const float* __restrict__ lr,
    const float* __restrict__ ft,
    const float* __restrict__ W,
    float* __restrict__ out)
{
    __shared__ float As[3][2048];
    __shared__ float Bs[3][2048];

    const int tid = threadIdx.x;
    const int tx = tid & 15, ty = tid >> 4;
    const int m0 = blockIdx.x * 128;
    const int n0 = blockIdx.y * 128;
    const int ch = tid >> 4;           // staging channel within 16-chunk
    const int lane = tid & 15;         // staging lane (8 floats)
    const int pu0 = swz(2 * lane), pu1 = swz(2 * lane + 1);
    const uint32_t aSb = smem_u32(As);
    const uint32_t bSb = smem_u32(Bs);

    ull acc[4][8];
#pragma unroll
    for (int i = 0; i < 4; i++)
#pragma unroll
        for (int j = 0; j < 8; j++) acc[i][j] = pack2(0.f, 0.f);

    auto stage = [&](int buf, int c) {
        const float* sA = (c >= 128) ? (ft + (c - 128) * NPIX_LR)
                                     : (lr + c * NPIX_LR);
        uint32_t ad = aSb + buf * 8192 + ch * 512;
        cp16(ad + pu0 * 16, sA + m0 + lane * 8);
        cp16(ad + pu1 * 16, sA + m0 + lane * 8 + 4);
        const float* sB = W + c * 256 + n0;
        uint32_t bd = bSb + buf * 8192 + ch * 512;
        cp16(bd + pu0 * 16, sB + lane * 8);
        cp16(bd + pu1 * 16, sB + lane * 8 + 4);
    };

    stage(0, ch);      CP_COMMIT();
    stage(1, 16 + ch); CP_COMMIT();

    const int ua0 = swz(2 * ty), ua1 = swz(2 * ty + 1);
    const int ub0 = swz(2 * tx), ub1 = swz(2 * tx + 1);

    for (int i = 0; i < 16; i++) {
        if (i + 1 < 16) { CP_WAIT(1); } else { CP_WAIT(0); }
        __syncthreads();
        if (i + 2 < 16) { stage((i + 2) % 3, (i + 2) * 16 + ch); CP_COMMIT(); }
        const float* Ac = As[0] + (i % 3) * 2048;
        const float* Bc = Bs[0] + (i % 3) * 2048;
#pragma unroll
        for (int kk = 0; kk < 16; kk++) {
            ulonglong2 aA = *(const ulonglong2*)&Ac[kk * 128 + ua0 * 4];
            ulonglong2 aB2 = *(const ulonglong2*)&Ac[kk * 128 + ua1 * 4];
            ull a_pk[4] = {aA.x, aA.y, aB2.x, aB2.y};
            float4 bv0 = *(const float4*)&Bc[kk * 128 + ub0 * 4];
            float4 bv1 = *(const float4*)&Bc[kk * 128 + ub1 * 4];
            ull b_pk[8];
            b_pk[0] = pack2(bv0.x, bv0.x); b_pk[1] = pack2(bv0.y, bv0.y);
            b_pk[2] = pack2(bv0.z, bv0.z); b_pk[3] = pack2(bv0.w, bv0.w);
            b_pk[4] = pack2(bv1.x, bv1.x); b_pk[5] = pack2(bv1.y, bv1.y);
            b_pk[6] = pack2(bv1.z, bv1.z); b_pk[7] = pack2(bv1.w, bv1.w);
#pragma unroll
            for (int p = 0; p < 4; p++)
#pragma unroll
                for (int j = 0; j < 8; j++)
                    acc[p][j] = fma2(a_pk[p], b_pk[j], acc[p][j]);
        }
    }

#pragma unroll
    for (int p = 0; p < 4; p++) {
        float2 u[8];
#pragma unroll
        for (int j = 0; j < 8; j++) u[j] = unpack2(acc[p][j]);
        float* r0 = out + (m0 + ty * 8 + 2 * p) * 256 + n0 + tx * 8;
        float* r1 = r0 + 256;
        *(float4*)r0       = make_float4(u[0].x, u[1].x, u[2].x, u[3].x);
        *(float4*)(r0 + 4) = make_float4(u[4].x, u[5].x, u[6].x, u[7].x);
        *(float4*)r1       = make_float4(u[0].y, u[1].y, u[2].y, u[3].y);
        *(float4*)(r1 + 4) = make_float4(u[4].y, u[5].y, u[6].y, u[7].y);
    }
}

// ---------------------------------------------------------------------------
// Fused tail. One block = 32 consecutive HR points = 128 MLP rows.
//   phase0: hg[32][256] = hr_rows[32][128] @ W1[256:384,:] + b1  (f32x2)
//   layer2: D[128,128] = relu(h1)[128,256] @ W2  (f32x2, 8x8/thread)
//   layer3: C3[128,32] = relu(D+b2)[128,128] @ W3 (f32x2 GEMM, k-split 2)
//   blend:  softmax over 4 quadrants, channel-major store.
//
// smem byte map (107136 total):
//   phase 0: hrs @0 (16384 = 128ch x 32pt), Wcs0 @16384 (16384, swz units),
//            Wcs1 @32768 (16384)  [Wcs1 overlaps hg; sync before hg write]
//   phase A: As @0 (16896), Bs @16896 (16384), hg @33280 (32x260 = 33280)
//   phase B: A3 @0 (67584, swz units), W3s @67584 (16384), C3s @83968 (16896)
//   persist @100864: w384 1024 | w385 @101888 | b2s @102912 512 |
//     b3s @103424 128 | rely @103552 512 | relx @104064 512 | gcs @104576 512 |
//     wq @105088 512 | nbr @105600 512 | b1s @106112 1024    end 107136
// ---------------------------------------------------------------------------
#define TAIL_SMEM_BYTES 107136

__global__ __launch_bounds__(256, 2) void fused_tail(
    const float* __restrict__ feat,
    const float* __restrict__ hr,
    const float* __restrict__ W1,
    const float* __restrict__ b1,
    const float* __restrict__ W2,
    const float* __restrict__ b2,
    const float* __restrict__ W3,
    const float* __restrict__ b3,
    float* __restrict__ out)
{
    extern __shared__ char smem[];
    float* hrs   = (float*)(smem);            // [c][pt] 128x32 (phase 0)
    float* Wcs0  = (float*)(smem + 16384);    // [kk][256] swz units (phase 0)
    float* Wcs1  = (float*)(smem + 32768);    // [kk][256] swz units (phase 0)
    float* As    = (float*)(smem);            // [kk][r] pitch 132 (phase A)
    float* Bs    = (float*)(smem + 16896);    // [kk][128], swizzled units
    float* hg    = (float*)(smem + 33280);    // [pt][260] (phase A)
    float* A3    = (float*)(smem);            // [k2][132], swz units (phase B)
    float* W3s   = (float*)(smem + 67584);    // [k2][32]
    float* C3s   = (float*)(smem + 83968);    // [r][33]
    float* w384s = (float*)(smem + 100864);
    float* w385s = (float*)(smem + 101888);
    float* b2s   = (float*)(smem + 102912);
    float* b3s   = (float*)(smem + 103424);
    float* rely  = (float*)(smem + 103552);
    float* relx  = (float*)(smem + 104064);
    float* gcs   = (float*)(smem + 104576);
    float* wq    = (float*)(smem + 105088);
    int*   nbr   = (int*)  (smem + 105600);
    float* b1s   = (float*)(smem + 106112);

    const int tid = threadIdx.x;
    const int p0  = blockIdx.x * 32;
    const int Y   = p0 >> 8;
    const int Xb  = p0 & 255;
    const float* W1g = W1 + 256 * 256;   // guide rows of W1 [128][256]
    const uint32_t wcs0_u = smem_u32(Wcs0);
    const uint32_t wcs1_u = smem_u32(Wcs1);

    // cp.async stage of a W1g chunk into Wcs buffer (swizzled units)
    auto stageW = [&](int buf, int chk) {
        uint32_t wb = buf ? wcs1_u : wcs0_u;
#pragma unroll
        for (int i = 0; i < 4; i++) {
            int e = tid + 256 * i;            // 1024 float4 units
            int kk = e >> 6, u = e & 63;
            cp16(wb + kk * 1024 + swz(u) * 16,
                 W1g + (chk * 16 + kk) * 256 + u * 4);
        }
    };

    // prologue: stage W chunk 0 ASAP (overlaps with everything below)
    stageW(0, 0); CP_COMMIT();

    // persist loads (regions disjoint from phase 0/A buffers)
    w384s[tid] = W1[384 * 256 + tid];
    w385s[tid] = W1[385 * 256 + tid];
    b1s[tid]   = b1[tid];
    if (tid < 128) b2s[tid] = b2[tid];
    if (tid < 32)  b3s[tid] = b3[tid];
#pragma unroll
    for (int i = 0; i < 16; i++) W3s[tid + 256 * i] = W3[tid + 256 * i];

    // per-row metadata + gating dots
    if (tid < 128) {
        int pt = tid >> 2, q = tid & 3;
        int X = Xb + pt;
        int vx = (q & 2) ? 1 : -1;        // perturbs Y (H axis)
        int vy = (q & 1) ? 1 : -1;        // perturbs X (W axis)
        int iy = (Y + vx) >> 1;           // exact nearest-sample reduction
        int ix = (X + vy) >> 1;
        bool ok = ((unsigned)iy < (unsigned)H_LR) && ((unsigned)ix < (unsigned)W_LR);
        int np = iy * W_LR + ix;
        nbr[tid]  = ok ? np : -1;
        rely[tid] = ok ? ((float)(Y - 2 * iy) - 0.5f) : ((float)Y + 0.5f - 128.0f);
        relx[tid] = ok ? ((float)(X - 2 * ix) - 0.5f) : ((float)X + 0.5f - 128.0f);
        float g = 0.f;
        if (ok) {
            int bp = (Y >> 1) * W_LR + (X >> 1);
#pragma unroll
            for (int c = 0; c < 3; c++)
                g = fmaf(feat[(124 + c) * NPIX_LR + bp],
                         feat[(124 + c) * NPIX_LR + np], g);
        }
        gcs[tid] = g;
    }

    // load hr rows: hrs[c][pt], coalesced 128B per channel
#pragma unroll
    for (int i = 0; i < 16; i++) {
        int e = tid + 256 * i;            // 0..4095
        int c = e >> 5, pt = e & 31;
        hrs[c * 32 + pt] = hr[c * NPTS + p0 + pt];
    }
    __syncthreads();

    // layer-2 metadata + early g_h1f prefetch (latency hidden under phase 0)
    const int rB  = tid & 127;            // build row
    const int khB = tid >> 7;             // k half
    const float ryB = rely[rB], rxB = relx[rB];
    const int nbB = nbr[rB];
    float4 pf[4];
#pragma unroll
    for (int j = 0; j < 4; j++) pf[j] = make_float4(0.f, 0.f, 0.f, 0.f);
    if (nbB >= 0) {
        const float* fr = g_h1f + nbB * 256 + khB * 16;
#pragma unroll
        for (int j = 0; j < 4; j++) pf[j] = *(const float4*)&fr[j * 4];
    }

    if (tid < 32) {
        float g0 = gcs[tid * 4 + 0], g1 = gcs[tid * 4 + 1];
        float g2 = gcs[tid * 4 + 2], g3 = gcs[tid * 4 + 3];
        float m = fmaxf(fmaxf(g0, g1), fmaxf(g2, g3));
        float e0 = expf(g0 - m), e1 = expf(g1 - m), e2 = expf(g2 - m), e3 = expf(g3 - m);
        float inv = 1.0f / (e0 + e1 + e2 + e3);
        wq[tid * 4 + 0] = e0 * inv;
        wq[tid * 4 + 1] = e1 * inv;
        wq[tid * 4 + 2] = e2 * inv;
        wq[tid * 4 + 3] = e3 * inv;
    }

    // ---- phase 0: hg = hrs^T @ W1g (+b1) ----
    // thread = (ptg: 4-pt group, cg: 8-col group); acc packed along points.
    // per kk: 1 LDS.128 a (broadcast) + 4 dup movs + 2 LDS.128 W (direct ull,
    // swizzle-conflict-free) + 16 FFMA2.
    {
        const int ptg = tid >> 5;         // 0..7 -> pts ptg*4..+3
        const int cg  = tid & 31;         // cols cg*8..+7
        const int u0 = swz(2 * cg), u1 = swz(2 * cg + 1);
        ull acc0[4][4];                   // [pt-pair? no: pt][col-pair]
#pragma unroll
        for (int p = 0; p < 4; p++)
#pragma unroll
            for (int j = 0; j < 4; j++) acc0[p][j] = pack2(0.f, 0.f);

        for (int chk = 0; chk < 8; chk++) {
            CP_WAIT(0);
            __syncthreads();              // chunk chk ready; prior reads done
            if (chk < 7) { stageW((chk + 1) & 1, chk + 1); CP_COMMIT(); }
            const float* wc = (chk & 1) ? Wcs1 : Wcs0;
#pragma unroll
            for (int kk = 0; kk < 16; kk++) {
                int c = chk * 16 + kk;
                float4 a4 = *(const float4*)&hrs[c * 32 + ptg * 4];
                ull ad[4] = {pack2(a4.x, a4.x), pack2(a4.y, a4.y),
                             pack2(a4.z, a4.z), pack2(a4.w, a4.w)};
                ulonglong2 w01 = *(const ulonglong2*)&wc[kk * 256 + u0 * 4];
                ulonglong2 w23 = *(const ulonglong2*)&wc[kk * 256 + u1 * 4];
                ull wv[4] = {w01.x, w01.y, w23.x, w23.y};
#pragma unroll
                for (int p = 0; p < 4; p++)
#pragma unroll
                    for (int j = 0; j < 4; j++)
                        acc0[p][j] = fma2(ad[p], wv[j], acc0[p][j]);
            }
        }
        __syncthreads();                  // all Wcs reads done (hg overlaps Wcs1)
        // write hg (+b1): float2 along n
#pragma unroll
        for (int p = 0; p < 4; p++) {
            int pt = ptg * 4 + p;
#pragma unroll
            for (int j = 0; j < 4; j++) {
                float2 u = unpack2(acc0[p][j]);
                int n = cg * 8 + 2 * j;
                u.x += b1s[n];
                u.y += b1s[n + 1];
                *(float2*)&hg[pt * 260 + n] = u;
            }
        }
    }

    // ---- layer 2: 8 chunks of K=32 ----
    const int tx = tid & 15, ty = tid >> 4;
    const int ub0 = swz(2 * tx), ub1 = swz(2 * tx + 1);
    ull acc[4][8];
#pragma unroll
    for (int i = 0; i < 4; i++)
#pragma unroll
        for (int j = 0; j < 8; j++) acc[i][j] = pack2(0.f, 0.f);

    for (int k0 = 0; k0 < 256; k0 += 32) {
        __syncthreads();                  // hg visible / prev inner done
        // build relu(h1) chunk: As[kk][rB], conflict-free STS
        {
            const float* hrow = hg + (rB >> 2) * 260 + k0 + khB * 16;
#pragma unroll
            for (int j = 0; j < 4; j++) {
                float4 h = *(const float4*)&hrow[j * 4];
                float4 f = pf[j];
#pragma unroll
                for (int t = 0; t < 4; t++) {
                    int kk = khB * 16 + j * 4 + t;
                    float v = (&h.x)[t] + (&f.x)[t];
                    v = fmaf(ryB, w384s[k0 + kk], v);
                    v = fmaf(rxB, w385s[k0 + kk], v);
                    As[kk * 132 + rB] = fmaxf(v, 0.f);
                }
            }
        }
        // stage W2 chunk with unit swizzle
#pragma unroll
        for (int i = 0; i < 4; i++) {
            int e = tid + 256 * i;
            int kk = e >> 5, u = e & 31;
            *(float4*)&Bs[kk * 128 + swz(u) * 4] =
                *(const float4*)&W2[(k0 + kk) * 128 + u * 4];
        }
        // prefetch next g_h1f half-chunk
        if (k0 < 224 && nbB >= 0) {
            const float* fr = g_h1f + nbB * 256 + k0 + 32 + khB * 16;
#pragma unroll
            for (int j = 0; j < 4; j++) pf[j] = *(const float4*)&fr[j * 4];
        }
        __syncthreads();                  // As/Bs visible
#pragma unroll
        for (int kk = 0; kk < 32; kk++) {
            ulonglong2 aA = *(const ulonglong2*)&As[kk * 132 + ty * 8];
            ulonglong2 aB = *(const ulonglong2*)&As[kk * 132 + ty * 8 + 4];
            ull a_pk[4] = {aA.x, aA.y, aB.x, aB.y};
            float4 bv0 = *(const float4*)&Bs[kk * 128 + ub0 * 4];
            float4 bv1 = *(const float4*)&Bs[kk * 128 + ub1 * 4];
            ull b_pk[8];
            b_pk[0] = pack2(bv0.x, bv0.x); b_pk[1] = pack2(bv0.y, bv0.y);
            b_pk[2] = pack2(bv0.z, bv0.z); b_pk[3] = pack2(bv0.w, bv0.w);
            b_pk[4] = pack2(bv1.x, bv1.x); b_pk[5] = pack2(bv1.y, bv1.y);
            b_pk[6] = pack2(bv1.z, bv1.z); b_pk[7] = pack2(bv1.w, bv1.w);
#pragma unroll
            for (int i = 0; i < 4; i++)
#pragma unroll
                for (int j = 0; j < 8; j++)
                    acc[i][j] = fma2(a_pk[i], b_pk[j], acc[i][j]);
        }
    }
    __syncthreads();                      // layer2 done; phase A smem free

    // relu(l2 + b2) -> A3 transposed [k2][r], 16B units swizzled by (k2>>3)&7
#pragma unroll
    for (int j = 0; j < 8; j++) {
        int k2 = tx * 8 + j;
        int sw = (k2 >> 3) & 7;
        float bb = b2s[k2];
#pragma unroll
        for (int i2 = 0; i2 < 4; i2++) {
            float2 u = unpack2(acc[i2][j]);
            float2 o;
            o.x = fmaxf(u.x + bb, 0.f);
            o.y = fmaxf(u.y + bb, 0.f);
            int ro = ty * 8 + 2 * i2;            // row offset within 128
            int ur = (ro >> 2) ^ sw;             // swizzled 16B unit
            int intra = ro & 3;
            *(float2*)&A3[k2 * 132 + ur * 4 + intra] = o;
        }
    }
    __syncthreads();

    // ---- layer 3: C3[128,32] = A3^T @ W3, k-split GEMM ----
    {
        const int kh = tid >> 7;          // k-half
        const int rem = tid & 127;
        const int rg = rem >> 3;          // rows rg*8..+7
        const int cg = rem & 7;           // cols cg*4..+3
        ull a3[4][4];
#pragma unroll
        for (int p = 0; p < 4; p++)
#pragma unroll
            for (int j = 0; j < 4; j++) a3[p][j] = pack2(0.f, 0.f);

        const float* w_base = W3s + (uint32_t)kh * 64 * 32 + cg * 4;
        for (int kt = 0; kt < 64; kt++) {
            int k2 = kh * 64 + kt;
            int sw = (k2 >> 3) & 7;
            const float* arow = A3 + k2 * 132;
            ulonglong2 aA = *(const ulonglong2*)&arow[((2 * rg) ^ sw) * 4];
            ulonglong2 aB = *(const ulonglong2*)&arow[((2 * rg + 1) ^ sw) * 4];
            float4 wv = *(const float4*)(w_base + kt * 32);
            ull w0 = pack2(wv.x, wv.x), w1 = pack2(wv.y, wv.y);
            ull w2 = pack2(wv.z, wv.z), w3v = pack2(wv.w, wv.w);
            ull ap[4] = {aA.x, aA.y, aB.x, aB.y};
#pragma unroll
            for (int p = 0; p < 4; p++) {
                a3[p][0] = fma2(ap[p], w0, a3[p][0]);
                a3[p][1] = fma2(ap[p], w1, a3[p][1]);
                a3[p][2] = fma2(ap[p], w2, a3[p][2]);
                a3[p][3] = fma2(ap[p], w3v, a3[p][3]);
            }
        }
        if (kh == 1) {
#pragma unroll
            for (int p = 0; p < 4; p++)
#pragma unroll
                for (int j = 0; j < 4; j++) {
                    float2 u = unpack2(a3[p][j]);
                    C3s[(rg * 8 + 2 * p) * 33 + cg * 4 + j]     = u.x;
                    C3s[(rg * 8 + 2 * p + 1) * 33 + cg * 4 + j] = u.y;
                }
        }
        __syncthreads();
        if (kh == 0) {
#pragma unroll
            for (int p = 0; p < 4; p++)
#pragma unroll
                for (int j = 0; j < 4; j++) {
                    float2 u = unpack2(a3[p][j]);
                    C3s[(rg * 8 + 2 * p) * 33 + cg * 4 + j]     += u.x;
                    C3s[(rg * 8 + 2 * p + 1) * 33 + cg * 4 + j] += u.y;
                }
        }
        __syncthreads();
    }

    // ---- softmax blend + coalesced channel-major store ----
#pragma unroll
    for (int i = 0; i < 4; i++) {
        int idx = tid + 256 * i;
        int pt = idx & 31, n = idx >> 5;
        float s = b3s[n];                 // sum(w)=1 -> bias post-blend
#pragma unroll
        for (int q = 0; q < 4; q++)
            s = fmaf(wq[pt * 4 + q], C3s[(pt * 4 + q) * 33 + n], s);
        out[n * NPTS + p0 + pt] = s;
    }
}

// ---------------------------------------------------------------------------
extern "C" void kernel_launch(void* const* d_in, const int* in_sizes, int n_in,
                              void* d_out, int out_size)
{
    const float* feat     = (const float*)d_in[0];
    const float* lr_guide = (const float*)d_in[1];
    const float* hr_guide = (const float*)d_in[2];
    const float* W1       = (const float*)d_in[3];
    const float* b1       = (const float*)d_in[4];
    const float* W2       = (const float*)d_in[5];
    const float* b2       = (const float*)d_in[6];
    const float* W3       = (const float*)d_in[7];
    const float* b3       = (const float*)d_in[8];
    float* out = (float*)d_out;

    void* h1f_p = nullptr;
    cudaGetSymbolAddress(&h1f_p, g_h1f);

    // K1: h1_feat[16384,256] = featc_T @ W1[0:256,:]
    {
        dim3 grid(NPIX_LR / 128, 256 / 128);
        gemm_l1f<<<grid, 256>>>(lr_guide, feat, W1, (float*)h1f_p);
    }
    // fused tail (computes h1_guide inline as phase 0)
    {
        cudaFuncSetAttribute(fused_tail, cudaFuncAttributeMaxDynamicSharedMemorySize,
                             TAIL_SMEM_BYTES);
        fused_tail<<<NPTS / 32, 256, TAIL_SMEM_BYTES>>>(
            feat, hr_guide, W1, b1, W2, b2, W3, b3, out);
    }
}

// round 10
// speedup vs baseline: 1.0365x; 1.0365x over previous
#include <cuda_runtime.h>
#include <math.h>
#include <stdint.h>

// ---------------------------------------------------------------------------
// Problem constants
//   feat[1,128,128,128] lr_guide[1,128,128,128] hr_guide[1,128,256,256]
//   W1[386,256] b1[256] W2[256,128] b2[128] W3[128,32] b3[32]
//   out [1,32,256,256] fp32
// ---------------------------------------------------------------------------
#define H_LR 128
#define W_LR 128
#define NPIX_LR (H_LR * W_LR)        // 16384
#define H_HR 256
#define W_HR 256
#define NPTS (H_HR * W_HR)           // 65536

typedef unsigned long long ull;

// ---- packed fp32x2 helpers (FFMA2 path) -----------------------------------
__device__ __forceinline__ ull pack2(float lo, float hi) {
    ull r; asm("mov.b64 %0, {%1,%2};" : "=l"(r) : "f"(lo), "f"(hi)); return r;
}
__device__ __forceinline__ ull fma2(ull a, ull b, ull c) {
    ull d; asm("fma.rn.f32x2 %0, %1, %2, %3;" : "=l"(d) : "l"(a), "l"(b), "l"(c));
    return d;
}
__device__ __forceinline__ float2 unpack2(ull v) {
    float2 f; asm("mov.b64 {%0,%1}, %2;" : "=f"(f.x), "=f"(f.y) : "l"(v)); return f;
}

// ---- cp.async helpers -----------------------------------------------------
__device__ __forceinline__ uint32_t smem_u32(const void* p) {
    uint32_t a;
    asm("{ .reg .u64 t; cvta.to.shared.u64 t, %1; cvt.u32.u64 %0, t; }"
        : "=r"(a) : "l"(p));
    return a;
}
__device__ __forceinline__ void cp16(uint32_t dst, const void* src) {
    asm volatile("cp.async.ca.shared.global [%0], [%1], 16;"
                 :: "r"(dst), "l"(src));
}
#define CP_COMMIT() asm volatile("cp.async.commit_group;" ::: "memory")
#define CP_WAIT(n)  asm volatile("cp.async.wait_group %0;" :: "n"(n) : "memory")

// 16B-unit XOR swizzle: distinct bank-quads within an 8-thread LDS phase
__device__ __forceinline__ int swz(int u) { return u ^ ((u >> 3) & 7); }

// Scratch (device globals: allocation-free per harness rules)
__device__ float g_h1f[NPIX_LR * 256];   // layer1 featc part per LR pixel (16 MB)
__device__ float g_h1g[NPTS * 256];      // layer1 guide part per HR point (64 MB)

// ---------------------------------------------------------------------------
// Layer-1 GEMM:  out[p][n] = sum_c A[p][c] * W[c*256 + n]
//   A[p][c] = (img1 && c>=128) ? img1[(c-128)*M + p] : img0[c*M + p]
// BM=128, BN=128, BK=16, 256 threads, 8x8/thread (f32x2),
// 3-stage cp.async pipeline, XOR-swizzled smem units.
// ---------------------------------------------------------------------------
__global__ __launch_bounds__(256, 2) void gemm_layer1(
    const float* __restrict__ img0,
    const float* __restrict__ img1,
    const float* __restrict__ W,
    float* __restrict__ out,
    int M, int K)
{
    __shared__ float As[3][2048];
    __shared__ float Bs[3][2048];

    const int tid = threadIdx.x;
    const int tx = tid & 15, ty = tid >> 4;
    const int m0 = blockIdx.x * 128;
    const int n0 = blockIdx.y * 128;
    const int ch = tid >> 4;           // staging channel within 16-chunk
    const int lane = tid & 15;         // staging lane (8 floats)
    const int pu0 = swz(2 * lane), pu1 = swz(2 * lane + 1);
    const uint32_t aSb = smem_u32(As);
    const uint32_t bSb = smem_u32(Bs);

    ull acc[4][8];
#pragma unroll
    for (int i = 0; i < 4; i++)
#pragma unroll
        for (int j = 0; j < 8; j++) acc[i][j] = pack2(0.f, 0.f);

    auto stage = [&](int buf, int c) {
        const float* sA = (img1 != nullptr && c >= 128)
                          ? (img1 + (c - 128) * M) : (img0 + c * M);
        uint32_t ad = aSb + buf * 8192 + ch * 512;
        cp16(ad + pu0 * 16, sA + m0 + lane * 8);
        cp16(ad + pu1 * 16, sA + m0 + lane * 8 + 4);
        const float* sB = W + c * 256 + n0;
        uint32_t bd = bSb + buf * 8192 + ch * 512;
        cp16(bd + pu0 * 16, sB + lane * 8);
        cp16(bd + pu1 * 16, sB + lane * 8 + 4);
    };

    const int nk = K >> 4;
    stage(0, ch);      CP_COMMIT();
    if (nk > 1) { stage(1, 16 + ch); CP_COMMIT(); }

    const int ua0 = swz(2 * ty), ua1 = swz(2 * ty + 1);
    const int ub0 = swz(2 * tx), ub1 = swz(2 * tx + 1);

    for (int i = 0; i < nk; i++) {
        if (i + 1 < nk) { CP_WAIT(1); } else { CP_WAIT(0); }
        __syncthreads();
        if (i + 2 < nk) { stage((i + 2) % 3, (i + 2) * 16 + ch); CP_COMMIT(); }
        const float* Ac = As[0] + (i % 3) * 2048;
        const float* Bc = Bs[0] + (i % 3) * 2048;
#pragma unroll
        for (int kk = 0; kk < 16; kk++) {
            ulonglong2 aA = *(const ulonglong2*)&Ac[kk * 128 + ua0 * 4];
            ulonglong2 aB2 = *(const ulonglong2*)&Ac[kk * 128 + ua1 * 4];
            ull a_pk[4] = {aA.x, aA.y, aB2.x, aB2.y};
            float4 bv0 = *(const float4*)&Bc[kk * 128 + ub0 * 4];
            float4 bv1 = *(const float4*)&Bc[kk * 128 + ub1 * 4];
            ull b_pk[8];
            b_pk[0] = pack2(bv0.x, bv0.x); b_pk[1] = pack2(bv0.y, bv0.y);
            b_pk[2] = pack2(bv0.z, bv0.z); b_pk[3] = pack2(bv0.w, bv0.w);
            b_pk[4] = pack2(bv1.x, bv1.x); b_pk[5] = pack2(bv1.y, bv1.y);
            b_pk[6] = pack2(bv1.z, bv1.z); b_pk[7] = pack2(bv1.w, bv1.w);
#pragma unroll
            for (int p = 0; p < 4; p++)
#pragma unroll
                for (int j = 0; j < 8; j++)
                    acc[p][j] = fma2(a_pk[p], b_pk[j], acc[p][j]);
        }
    }

#pragma unroll
    for (int p = 0; p < 4; p++) {
        float2 u[8];
#pragma unroll
        for (int j = 0; j < 8; j++) u[j] = unpack2(acc[p][j]);
        float* r0 = out + (m0 + ty * 8 + 2 * p) * 256 + n0 + tx * 8;
        float* r1 = r0 + 256;
        *(float4*)r0       = make_float4(u[0].x, u[1].x, u[2].x, u[3].x);
        *(float4*)(r0 + 4) = make_float4(u[4].x, u[5].x, u[6].x, u[7].x);
        *(float4*)r1       = make_float4(u[0].y, u[1].y, u[2].y, u[3].y);
        *(float4*)(r1 + 4) = make_float4(u[4].y, u[5].y, u[6].y, u[7].y);
    }
}

// ---------------------------------------------------------------------------
// Fused tail (R7 proven version, byte-identical math).
// One block = 32 consecutive HR points = 128 MLP rows.
//   layer2: D[128,128] = relu(h1)[128,256] @ W2  (f32x2, 8x8/thread)
//   layer3: C3[128,32] = relu(D+b2)[128,128] @ W3 (f32x2 GEMM, k-split 2)
//   blend:  softmax over 4 quadrants, channel-major store.
//
// smem byte map (106112 total):
//   phase A: As @0 (16896), Bs @16896 (16384, swz units),
//            hg @33280 (32x260 = 33280)                      end 66560
//   phase B: A3 @0 (67584, swz units), W3s @67584 (16384), C3s @83968 (16896)
//   persist @100864: w384 1024 | w385 @101888 | b2s @102912 512 |
//     b3s @103424 128 | rely @103552 512 | relx @104064 512 | gcs @104576 512 |
//     wq @105088 512 | nbr @105600 512                        end 106112
// ---------------------------------------------------------------------------
#define TAIL_SMEM_BYTES 106112

__global__ __launch_bounds__(256, 2) void fused_tail(
    const float* __restrict__ feat,
    const float* __restrict__ W1,
    const float* __restrict__ b1,
    const float* __restrict__ W2,
    const float* __restrict__ b2,
    const float* __restrict__ W3,
    const float* __restrict__ b3,
    float* __restrict__ out)
{
    extern __shared__ char smem[];
    float* As    = (float*)(smem);            // [kk][r] pitch 132 (phase A)
    float* Bs    = (float*)(smem + 16896);    // [kk][128], swizzled units
    float* hg    = (float*)(smem + 33280);    // [pt][260] (phase A)
    float* A3    = (float*)(smem);            // [k2][132], swz units (phase B)
    float* W3s   = (float*)(smem + 67584);    // [k2][32]
    float* C3s   = (float*)(smem + 83968);    // [r][33]
    float* w384s = (float*)(smem + 100864);
    float* w385s = (float*)(smem + 101888);
    float* b2s   = (float*)(smem + 102912);
    float* b3s   = (float*)(smem + 103424);
    float* rely  = (float*)(smem + 103552);
    float* relx  = (float*)(smem + 104064);
    float* gcs   = (float*)(smem + 104576);
    float* wq    = (float*)(smem + 105088);
    int*   nbr   = (int*)  (smem + 105600);

    const int tid = threadIdx.x;
    const int p0  = blockIdx.x * 32;
    const int Y   = p0 >> 8;
    const int Xb  = p0 & 255;

    // small vectors (regions disjoint from phase A -> load now)
    w384s[tid] = W1[384 * 256 + tid];
    w385s[tid] = W1[385 * 256 + tid];
    if (tid < 128) b2s[tid] = b2[tid];
    if (tid < 32)  b3s[tid] = b3[tid];
#pragma unroll
    for (int i = 0; i < 16; i++) W3s[tid + 256 * i] = W3[tid + 256 * i];

    // per-row metadata + gating dots
    if (tid < 128) {
        int pt = tid >> 2, q = tid & 3;
        int X = Xb + pt;
        int vx = (q & 2) ? 1 : -1;        // perturbs Y (H axis)
        int vy = (q & 1) ? 1 : -1;        // perturbs X (W axis)
        int iy = (Y + vx) >> 1;           // exact nearest-sample reduction
        int ix = (X + vy) >> 1;
        bool ok = ((unsigned)iy < (unsigned)H_LR) && ((unsigned)ix < (unsigned)W_LR);
        int np = iy * W_LR + ix;
        nbr[tid]  = ok ? np : -1;
        rely[tid] = ok ? ((float)(Y - 2 * iy) - 0.5f) : ((float)Y + 0.5f - 128.0f);
        relx[tid] = ok ? ((float)(X - 2 * ix) - 0.5f) : ((float)X + 0.5f - 128.0f);
        float g = 0.f;
        if (ok) {
            int bp = (Y >> 1) * W_LR + (X >> 1);
#pragma unroll
            for (int c = 0; c < 3; c++)
                g = fmaf(feat[(124 + c) * NPIX_LR + bp],
                         feat[(124 + c) * NPIX_LR + np], g);
        }
        gcs[tid] = g;
    }

    // stage full hg (+b1) once: 32 pts x 256 k, pitch 260
#pragma unroll
    for (int i = 0; i < 8; i++) {
        int e = tid + 256 * i;            // float4 slots
        int pt = e >> 6, kq = (e & 63) * 4;
        float4 v = *(const float4*)&g_h1g[(p0 + pt) * 256 + kq];
        float4 bv = *(const float4*)&b1[kq];
        v.x += bv.x; v.y += bv.y; v.z += bv.z; v.w += bv.w;
        *(float4*)&hg[pt * 260 + kq] = v;
    }
    __syncthreads();

    if (tid < 32) {
        float g0 = gcs[tid * 4 + 0], g1 = gcs[tid * 4 + 1];
        float g2 = gcs[tid * 4 + 2], g3 = gcs[tid * 4 + 3];
        float m = fmaxf(fmaxf(g0, g1), fmaxf(g2, g3));
        float e0 = expf(g0 - m), e1 = expf(g1 - m), e2 = expf(g2 - m), e3 = expf(g3 - m);
        float inv = 1.0f / (e0 + e1 + e2 + e3);
        wq[tid * 4 + 0] = e0 * inv;
        wq[tid * 4 + 1] = e1 * inv;
        wq[tid * 4 + 2] = e2 * inv;
        wq[tid * 4 + 3] = e3 * inv;
    }

    // As-build thread mapping: one row per thread, half the k-chunk
    const int rB  = tid & 127;            // build row (warp spans 32 rows)
    const int khB = tid >> 7;             // k half (16 k's of the 32-chunk)
    const float ryB = rely[rB], rxB = relx[rB];
    const int nbB = nbr[rB];

    float4 pf[4];                          // prefetched g_h1f half-chunk
#pragma unroll
    for (int j = 0; j < 4; j++) pf[j] = make_float4(0.f, 0.f, 0.f, 0.f);
    if (nbB >= 0) {
        const float* fr = g_h1f + nbB * 256 + khB * 16;
#pragma unroll
        for (int j = 0; j < 4; j++) pf[j] = *(const float4*)&fr[j * 4];
    }

    // ---- layer 2: 8 chunks of K=32 ----
    const int tx = tid & 15, ty = tid >> 4;
    const int ub0 = swz(2 * tx), ub1 = swz(2 * tx + 1);
    ull acc[4][8];
#pragma unroll
    for (int i = 0; i < 4; i++)
#pragma unroll
        for (int j = 0; j < 8; j++) acc[i][j] = pack2(0.f, 0.f);

    for (int k0 = 0; k0 < 256; k0 += 32) {
        __syncthreads();                  // prev inner done reading As/Bs
        // build relu(h1) chunk: As[kk][rB], conflict-free STS
        {
            const float* hrow = hg + (rB >> 2) * 260 + k0 + khB * 16;
#pragma unroll
            for (int j = 0; j < 4; j++) {
                float4 h = *(const float4*)&hrow[j * 4];
                float4 f = pf[j];
#pragma unroll
                for (int t = 0; t < 4; t++) {
                    int kk = khB * 16 + j * 4 + t;
                    float v = (&h.x)[t] + (&f.x)[t];
                    v = fmaf(ryB, w384s[k0 + kk], v);
                    v = fmaf(rxB, w385s[k0 + kk], v);
                    As[kk * 132 + rB] = fmaxf(v, 0.f);
                }
            }
        }
        // stage W2 chunk with unit swizzle
#pragma unroll
        for (int i = 0; i < 4; i++) {
            int e = tid + 256 * i;
            int kk = e >> 5, u = e & 31;
            *(float4*)&Bs[kk * 128 + swz(u) * 4] =
                *(const float4*)&W2[(k0 + kk) * 128 + u * 4];
        }
        // prefetch next g_h1f half-chunk
        if (k0 < 224 && nbB >= 0) {
            const float* fr = g_h1f + nbB * 256 + k0 + 32 + khB * 16;
#pragma unroll
            for (int j = 0; j < 4; j++) pf[j] = *(const float4*)&fr[j * 4];
        }
        __syncthreads();                  // As/Bs visible
#pragma unroll
        for (int kk = 0; kk < 32; kk++) {
            ulonglong2 aA = *(const ulonglong2*)&As[kk * 132 + ty * 8];
            ulonglong2 aB = *(const ulonglong2*)&As[kk * 132 + ty * 8 + 4];
            ull a_pk[4] = {aA.x, aA.y, aB.x, aB.y};
            float4 bv0 = *(const float4*)&Bs[kk * 128 + ub0 * 4];
            float4 bv1 = *(const float4*)&Bs[kk * 128 + ub1 * 4];
            ull b_pk[8];
            b_pk[0] = pack2(bv0.x, bv0.x); b_pk[1] = pack2(bv0.y, bv0.y);
            b_pk[2] = pack2(bv0.z, bv0.z); b_pk[3] = pack2(bv0.w, bv0.w);
            b_pk[4] = pack2(bv1.x, bv1.x); b_pk[5] = pack2(bv1.y, bv1.y);
            b_pk[6] = pack2(bv1.z, bv1.z); b_pk[7] = pack2(bv1.w, bv1.w);
#pragma unroll
            for (int i = 0; i < 4; i++)
#pragma unroll
                for (int j = 0; j < 8; j++)
                    acc[i][j] = fma2(a_pk[i], b_pk[j], acc[i][j]);
        }
    }
    __syncthreads();                      // layer2 done; phase A smem free

    // relu(l2 + b2) -> A3 transposed [k2][r], 16B units swizzled by (k2>>3)&7
#pragma unroll
    for (int j = 0; j < 8; j++) {
        int k2 = tx * 8 + j;
        int sw = (k2 >> 3) & 7;
        float bb = b2s[k2];
#pragma unroll
        for (int i2 = 0; i2 < 4; i2++) {
            float2 u = unpack2(acc[i2][j]);
            float2 o;
            o.x = fmaxf(u.x + bb, 0.f);
            o.y = fmaxf(u.y + bb, 0.f);
            int ro = ty * 8 + 2 * i2;            // row offset within 128
            int ur = (ro >> 2) ^ sw;             // swizzled 16B unit
            int intra = ro & 3;
            *(float2*)&A3[k2 * 132 + ur * 4 + intra] = o;
        }
    }
    __syncthreads();

    // ---- layer 3: C3[128,32] = A3^T @ W3, k-split GEMM ----
    {
        const int kh = tid >> 7;          // k-half
        const int rem = tid & 127;
        const int rg = rem >> 3;          // rows rg*8..+7
        const int cg = rem & 7;           // cols cg*4..+3
        ull a3[4][4];
#pragma unroll
        for (int p = 0; p < 4; p++)
#pragma unroll
            for (int j = 0; j < 4; j++) a3[p][j] = pack2(0.f, 0.f);

        const float* w_base = W3s + (uint32_t)kh * 64 * 32 + cg * 4;
        for (int kt = 0; kt < 64; kt++) {
            int k2 = kh * 64 + kt;
            int sw = (k2 >> 3) & 7;
            const float* arow = A3 + k2 * 132;
            ulonglong2 aA = *(const ulonglong2*)&arow[((2 * rg) ^ sw) * 4];
            ulonglong2 aB = *(const ulonglong2*)&arow[((2 * rg + 1) ^ sw) * 4];
            float4 wv = *(const float4*)(w_base + kt * 32);
            ull w0 = pack2(wv.x, wv.x), w1 = pack2(wv.y, wv.y);
            ull w2 = pack2(wv.z, wv.z), w3v = pack2(wv.w, wv.w);
            ull ap[4] = {aA.x, aA.y, aB.x, aB.y};
#pragma unroll
            for (int p = 0; p < 4; p++) {
                a3[p][0] = fma2(ap[p], w0, a3[p][0]);
                a3[p][1] = fma2(ap[p], w1, a3[p][1]);
                a3[p][2] = fma2(ap[p], w2, a3[p][2]);
                a3[p][3] = fma2(ap[p], w3v, a3[p][3]);
            }
        }
        if (kh == 1) {
#pragma unroll
            for (int p = 0; p < 4; p++)
#pragma unroll
                for (int j = 0; j < 4; j++) {
                    float2 u = unpack2(a3[p][j]);
                    C3s[(rg * 8 + 2 * p) * 33 + cg * 4 + j]     = u.x;
                    C3s[(rg * 8 + 2 * p + 1) * 33 + cg * 4 + j] = u.y;
                }
        }
        __syncthreads();
        if (kh == 0) {
#pragma unroll
            for (int p = 0; p < 4; p++)
#pragma unroll
                for (int j = 0; j < 4; j++) {
                    float2 u = unpack2(a3[p][j]);
                    C3s[(rg * 8 + 2 * p) * 33 + cg * 4 + j]     += u.x;
                    C3s[(rg * 8 + 2 * p + 1) * 33 + cg * 4 + j] += u.y;
                }
        }
        __syncthreads();
    }

    // ---- softmax blend + coalesced channel-major store ----
#pragma unroll
    for (int i = 0; i < 4; i++) {
        int idx = tid + 256 * i;
        int pt = idx & 31, n = idx >> 5;
        float s = b3s[n];                 // sum(w)=1 -> bias post-blend
#pragma unroll
        for (int q = 0; q < 4; q++)
            s = fmaf(wq[pt * 4 + q], C3s[(pt * 4 + q) * 33 + n], s);
        out[n * NPTS + p0 + pt] = s;
    }
}

// ---------------------------------------------------------------------------
extern "C" void kernel_launch(void* const* d_in, const int* in_sizes, int n_in,
                              void* d_out, int out_size)
{
    const float* feat     = (const float*)d_in[0];
    const float* lr_guide = (const float*)d_in[1];
    const float* hr_guide = (const float*)d_in[2];
    const float* W1       = (const float*)d_in[3];
    const float* b1       = (const float*)d_in[4];
    const float* W2       = (const float*)d_in[5];
    const float* b2       = (const float*)d_in[6];
    const float* W3       = (const float*)d_in[7];
    const float* b3       = (const float*)d_in[8];
    float* out = (float*)d_out;

    void* h1f_p = nullptr;
    void* h1g_p = nullptr;
    cudaGetSymbolAddress(&h1f_p, g_h1f);
    cudaGetSymbolAddress(&h1g_p, g_h1g);

    // K1: h1_feat[16384,256] = featc_T @ W1[0:256,:]
    {
        dim3 grid(NPIX_LR / 128, 256 / 128);
        gemm_layer1<<<grid, 256>>>(lr_guide, feat, W1, (float*)h1f_p,
                                   NPIX_LR, 256);
    }
    // K2: h1_guide[65536,256] = hr_guide_T @ W1[256:384,:]
    {
        dim3 grid(NPTS / 128, 256 / 128);
        gemm_layer1<<<grid, 256>>>(hr_guide, nullptr, W1 + 256 * 256,
                                   (float*)h1g_p, NPTS, 128);
    }
    // fused tail (R7 version)
    {
        cudaFuncSetAttribute(fused_tail, cudaFuncAttributeMaxDynamicSharedMemorySize,
                             TAIL_SMEM_BYTES);
        fused_tail<<<NPTS / 32, 256, TAIL_SMEM_BYTES>>>(
            feat, W1, b1, W2, b2, W3, b3, out);
    }
}

// round 11
// speedup vs baseline: 1.0524x; 1.0154x over previous
#include <cuda_runtime.h>
#include <math.h>
#include <stdint.h>

// ---------------------------------------------------------------------------
// Problem constants
//   feat[1,128,128,128] lr_guide[1,128,128,128] hr_guide[1,128,256,256]
//   W1[386,256] b1[256] W2[256,128] b2[128] W3[128,32] b3[32]
//   out [1,32,256,256] fp32
// ---------------------------------------------------------------------------
#define H_LR 128
#define W_LR 128
#define NPIX_LR (H_LR * W_LR)        // 16384
#define H_HR 256
#define W_HR 256
#define NPTS (H_HR * W_HR)           // 65536

typedef unsigned long long ull;

// ---- packed fp32x2 helpers (FFMA2 path) -----------------------------------
__device__ __forceinline__ ull pack2(float lo, float hi) {
    ull r; asm("mov.b64 %0, {%1,%2};" : "=l"(r) : "f"(lo), "f"(hi)); return r;
}
__device__ __forceinline__ ull fma2(ull a, ull b, ull c) {
    ull d; asm("fma.rn.f32x2 %0, %1, %2, %3;" : "=l"(d) : "l"(a), "l"(b), "l"(c));
    return d;
}
__device__ __forceinline__ float2 unpack2(ull v) {
    float2 f; asm("mov.b64 {%0,%1}, %2;" : "=f"(f.x), "=f"(f.y) : "l"(v)); return f;
}

// ---- cp.async helpers -----------------------------------------------------
__device__ __forceinline__ uint32_t smem_u32(const void* p) {
    uint32_t a;
    asm("{ .reg .u64 t; cvta.to.shared.u64 t, %1; cvt.u32.u64 %0, t; }"
        : "=r"(a) : "l"(p));
    return a;
}
__device__ __forceinline__ void cp16(uint32_t dst, const void* src) {
    asm volatile("cp.async.ca.shared.global [%0], [%1], 16;"
                 :: "r"(dst), "l"(src));
}
#define CP_COMMIT() asm volatile("cp.async.commit_group;" ::: "memory")
#define CP_WAIT(n)  asm volatile("cp.async.wait_group %0;" :: "n"(n) : "memory")

// 16B-unit XOR swizzle: distinct bank-quads within an 8-thread LDS phase
__device__ __forceinline__ int swz(int u) { return u ^ ((u >> 3) & 7); }

// Scratch (device globals: allocation-free per harness rules)
__device__ float g_h1f[NPIX_LR * 256];   // layer1 featc part per LR pixel (16 MB)
__device__ float g_h1g[NPTS * 256];      // layer1 guide part (+b1) per HR point

// ---------------------------------------------------------------------------
// Merged layer-1 GEMMs, one launch:
//   blocks [0,256):    h1f[16384,256] = featc_T @ W1[0:256,:]
//   blocks [256,1280): h1g[65536,256] = hr_T    @ W1[256:384,:] + b1
// BM=128, BN=128, BK=16, 256 threads, 8x8/thread (f32x2),
// 4-stage cp.async pipeline, XOR-swizzled smem units.
// ---------------------------------------------------------------------------
__global__ __launch_bounds__(256, 2) void gemm_l1_merged(
    const float* __restrict__ lr,
    const float* __restrict__ ft,
    const float* __restrict__ hrg,
    const float* __restrict__ W1,
    const float* __restrict__ b1,
    float* __restrict__ h1f,
    float* __restrict__ h1g)
{
    __shared__ float As[4][2048];
    __shared__ float Bs[4][2048];

    const int tid = threadIdx.x;
    const int tx = tid & 15, ty = tid >> 4;

    const float *img0, *img1, *W, *outp_base;
    float* outp;
    int M, K, mt, nt, addb1;
    {
        int bx = blockIdx.x;
        if (bx < 256) {                   // K1 (longer blocks, scheduled first)
            img0 = lr; img1 = ft; W = W1; outp_base = nullptr;
            M = NPIX_LR; K = 256; addb1 = 0;
            mt = bx >> 1; nt = bx & 1;
            outp = h1f;
        } else {                          // K2
            bx -= 256;
            img0 = hrg; img1 = nullptr; W = W1 + 256 * 256;
            M = NPTS; K = 128; addb1 = 1;
            mt = bx >> 1; nt = bx & 1;
            outp = h1g;
        }
        (void)outp_base;
    }
    const int m0 = mt * 128;
    const int n0 = nt * 128;

    const int ch = tid >> 4;           // staging channel within 16-chunk
    const int lane = tid & 15;         // staging lane (8 floats)
    const int pu0 = swz(2 * lane), pu1 = swz(2 * lane + 1);
    const uint32_t aSb = smem_u32(As);
    const uint32_t bSb = smem_u32(Bs);

    ull acc[4][8];
#pragma unroll
    for (int i = 0; i < 4; i++)
#pragma unroll
        for (int j = 0; j < 8; j++) acc[i][j] = pack2(0.f, 0.f);

    auto stage = [&](int buf, int c) {
        const float* sA = (img1 != nullptr && c >= 128)
                          ? (img1 + (c - 128) * M) : (img0 + c * M);
        uint32_t ad = aSb + buf * 8192 + ch * 512;
        cp16(ad + pu0 * 16, sA + m0 + lane * 8);
        cp16(ad + pu1 * 16, sA + m0 + lane * 8 + 4);
        const float* sB = W + c * 256 + n0;
        uint32_t bd = bSb + buf * 8192 + ch * 512;
        cp16(bd + pu0 * 16, sB + lane * 8);
        cp16(bd + pu1 * 16, sB + lane * 8 + 4);
    };

    const int nk = K >> 4;                 // 16 (K1) or 8 (K2)
    stage(0, ch);           CP_COMMIT();
    stage(1, 16 + ch);      CP_COMMIT();
    stage(2, 32 + ch);      CP_COMMIT();

    const int ua0 = swz(2 * ty), ua1 = swz(2 * ty + 1);
    const int ub0 = swz(2 * tx), ub1 = swz(2 * tx + 1);

    for (int i = 0; i < nk; i++) {
        int rem = nk - 1 - i;              // chunks still to consume after i
        if (rem >= 2)      { CP_WAIT(2); }
        else if (rem == 1) { CP_WAIT(1); }
        else               { CP_WAIT(0); }
        __syncthreads();                   // all threads done with buf (i-1)%4
        if (i + 3 < nk) { stage((i + 3) & 3, (i + 3) * 16 + ch); CP_COMMIT(); }
        const float* Ac = As[0] + (i & 3) * 2048;
        const float* Bc = Bs[0] + (i & 3) * 2048;
#pragma unroll
        for (int kk = 0; kk < 16; kk++) {
            ulonglong2 aA = *(const ulonglong2*)&Ac[kk * 128 + ua0 * 4];
            ulonglong2 aB2 = *(const ulonglong2*)&Ac[kk * 128 + ua1 * 4];
            ull a_pk[4] = {aA.x, aA.y, aB2.x, aB2.y};
            float4 bv0 = *(const float4*)&Bc[kk * 128 + ub0 * 4];
            float4 bv1 = *(const float4*)&Bc[kk * 128 + ub1 * 4];
            ull b_pk[8];
            b_pk[0] = pack2(bv0.x, bv0.x); b_pk[1] = pack2(bv0.y, bv0.y);
            b_pk[2] = pack2(bv0.z, bv0.z); b_pk[3] = pack2(bv0.w, bv0.w);
            b_pk[4] = pack2(bv1.x, bv1.x); b_pk[5] = pack2(bv1.y, bv1.y);
            b_pk[6] = pack2(bv1.z, bv1.z); b_pk[7] = pack2(bv1.w, bv1.w);
#pragma unroll
            for (int p = 0; p < 4; p++)
#pragma unroll
                for (int j = 0; j < 8; j++)
                    acc[p][j] = fma2(a_pk[p], b_pk[j], acc[p][j]);
        }
    }

    // epilogue: optional +b1 (K2 path), then 128x128 tile store
    float4 bb0 = make_float4(0.f, 0.f, 0.f, 0.f);
    float4 bb1 = make_float4(0.f, 0.f, 0.f, 0.f);
    if (addb1) {
        bb0 = *(const float4*)&b1[n0 + tx * 8];
        bb1 = *(const float4*)&b1[n0 + tx * 8 + 4];
    }
#pragma unroll
    for (int p = 0; p < 4; p++) {
        float2 u[8];
#pragma unroll
        for (int j = 0; j < 8; j++) u[j] = unpack2(acc[p][j]);
        float* r0 = outp + (size_t)(m0 + ty * 8 + 2 * p) * 256 + n0 + tx * 8;
        float* r1 = r0 + 256;
        *(float4*)r0       = make_float4(u[0].x + bb0.x, u[1].x + bb0.y,
                                         u[2].x + bb0.z, u[3].x + bb0.w);
        *(float4*)(r0 + 4) = make_float4(u[4].x + bb1.x, u[5].x + bb1.y,
                                         u[6].x + bb1.z, u[7].x + bb1.w);
        *(float4*)r1       = make_float4(u[0].y + bb0.x, u[1].y + bb0.y,
                                         u[2].y + bb0.z, u[3].y + bb0.w);
        *(float4*)(r1 + 4) = make_float4(u[4].y + bb1.x, u[5].y + bb1.y,
                                         u[6].y + bb1.z, u[7].y + bb1.w);
    }
}

// ---------------------------------------------------------------------------
// Fused tail (R7 proven version; hg staging is now a pure copy since b1 is
// folded into g_h1g by the producer).
// One block = 32 consecutive HR points = 128 MLP rows.
//   layer2: D[128,128] = relu(h1)[128,256] @ W2  (f32x2, 8x8/thread)
//   layer3: C3[128,32] = relu(D+b2)[128,128] @ W3 (f32x2 GEMM, k-split 2)
//   blend:  softmax over 4 quadrants, channel-major store.
//
// smem byte map (106112 total):
//   phase A: As @0 (16896), Bs @16896 (16384, swz units),
//            hg @33280 (32x260 = 33280)                      end 66560
//   phase B: A3 @0 (67584, swz units), W3s @67584 (16384), C3s @83968 (16896)
//   persist @100864: w384 1024 | w385 @101888 | b2s @102912 512 |
//     b3s @103424 128 | rely @103552 512 | relx @104064 512 | gcs @104576 512 |
//     wq @105088 512 | nbr @105600 512                        end 106112
// ---------------------------------------------------------------------------
#define TAIL_SMEM_BYTES 106112

__global__ __launch_bounds__(256, 2) void fused_tail(
    const float* __restrict__ feat,
    const float* __restrict__ W1,
    const float* __restrict__ W2,
    const float* __restrict__ b2,
    const float* __restrict__ W3,
    const float* __restrict__ b3,
    float* __restrict__ out)
{
    extern __shared__ char smem[];
    float* As    = (float*)(smem);            // [kk][r] pitch 132 (phase A)
    float* Bs    = (float*)(smem + 16896);    // [kk][128], swizzled units
    float* hg    = (float*)(smem + 33280);    // [pt][260] (phase A)
    float* A3    = (float*)(smem);            // [k2][132], swz units (phase B)
    float* W3s   = (float*)(smem + 67584);    // [k2][32]
    float* C3s   = (float*)(smem + 83968);    // [r][33]
    float* w384s = (float*)(smem + 100864);
    float* w385s = (float*)(smem + 101888);
    float* b2s   = (float*)(smem + 102912);
    float* b3s   = (float*)(smem + 103424);
    float* rely  = (float*)(smem + 103552);
    float* relx  = (float*)(smem + 104064);
    float* gcs   = (float*)(smem + 104576);
    float* wq    = (float*)(smem + 105088);
    int*   nbr   = (int*)  (smem + 105600);

    const int tid = threadIdx.x;
    const int p0  = blockIdx.x * 32;
    const int Y   = p0 >> 8;
    const int Xb  = p0 & 255;

    // small vectors (regions disjoint from phase A -> load now)
    w384s[tid] = W1[384 * 256 + tid];
    w385s[tid] = W1[385 * 256 + tid];
    if (tid < 128) b2s[tid] = b2[tid];
    if (tid < 32)  b3s[tid] = b3[tid];
#pragma unroll
    for (int i = 0; i < 16; i++) W3s[tid + 256 * i] = W3[tid + 256 * i];

    // per-row metadata + gating dots
    if (tid < 128) {
        int pt = tid >> 2, q = tid & 3;
        int X = Xb + pt;
        int vx = (q & 2) ? 1 : -1;        // perturbs Y (H axis)
        int vy = (q & 1) ? 1 : -1;        // perturbs X (W axis)
        int iy = (Y + vx) >> 1;           // exact nearest-sample reduction
        int ix = (X + vy) >> 1;
        bool ok = ((unsigned)iy < (unsigned)H_LR) && ((unsigned)ix < (unsigned)W_LR);
        int np = iy * W_LR + ix;
        nbr[tid]  = ok ? np : -1;
        rely[tid] = ok ? ((float)(Y - 2 * iy) - 0.5f) : ((float)Y + 0.5f - 128.0f);
        relx[tid] = ok ? ((float)(X - 2 * ix) - 0.5f) : ((float)X + 0.5f - 128.0f);
        float g = 0.f;
        if (ok) {
            int bp = (Y >> 1) * W_LR + (X >> 1);
#pragma unroll
            for (int c = 0; c < 3; c++)
                g = fmaf(feat[(124 + c) * NPIX_LR + bp],
                         feat[(124 + c) * NPIX_LR + np], g);
        }
        gcs[tid] = g;
    }

    // stage full hg once (b1 pre-folded by producer): 32 pts x 256 k, pitch 260
#pragma unroll
    for (int i = 0; i < 8; i++) {
        int e = tid + 256 * i;            // float4 slots
        int pt = e >> 6, kq = (e & 63) * 4;
        *(float4*)&hg[pt * 260 + kq] =
            *(const float4*)&g_h1g[(p0 + pt) * 256 + kq];
    }
    __syncthreads();

    if (tid < 32) {
        float g0 = gcs[tid * 4 + 0], g1 = gcs[tid * 4 + 1];
        float g2 = gcs[tid * 4 + 2], g3 = gcs[tid * 4 + 3];
        float m = fmaxf(fmaxf(g0, g1), fmaxf(g2, g3));
        float e0 = expf(g0 - m), e1 = expf(g1 - m), e2 = expf(g2 - m), e3 = expf(g3 - m);
        float inv = 1.0f / (e0 + e1 + e2 + e3);
        wq[tid * 4 + 0] = e0 * inv;
        wq[tid * 4 + 1] = e1 * inv;
        wq[tid * 4 + 2] = e2 * inv;
        wq[tid * 4 + 3] = e3 * inv;
    }

    // As-build thread mapping: one row per thread, half the k-chunk
    const int rB  = tid & 127;            // build row (warp spans 32 rows)
    const int khB = tid >> 7;             // k half (16 k's of the 32-chunk)
    const float ryB = rely[rB], rxB = relx[rB];
    const int nbB = nbr[rB];

    float4 pf[4];                          // prefetched g_h1f half-chunk
#pragma unroll
    for (int j = 0; j < 4; j++) pf[j] = make_float4(0.f, 0.f, 0.f, 0.f);
    if (nbB >= 0) {
        const float* fr = g_h1f + nbB * 256 + khB * 16;
#pragma unroll
        for (int j = 0; j < 4; j++) pf[j] = *(const float4*)&fr[j * 4];
    }

    // ---- layer 2: 8 chunks of K=32 ----
    const int tx = tid & 15, ty = tid >> 4;
    const int ub0 = swz(2 * tx), ub1 = swz(2 * tx + 1);
    ull acc[4][8];
#pragma unroll
    for (int i = 0; i < 4; i++)
#pragma unroll
        for (int j = 0; j < 8; j++) acc[i][j] = pack2(0.f, 0.f);

    for (int k0 = 0; k0 < 256; k0 += 32) {
        __syncthreads();                  // prev inner done reading As/Bs
        // build relu(h1) chunk: As[kk][rB], conflict-free STS
        {
            const float* hrow = hg + (rB >> 2) * 260 + k0 + khB * 16;
#pragma unroll
            for (int j = 0; j < 4; j++) {
                float4 h = *(const float4*)&hrow[j * 4];
                float4 f = pf[j];
#pragma unroll
                for (int t = 0; t < 4; t++) {
                    int kk = khB * 16 + j * 4 + t;
                    float v = (&h.x)[t] + (&f.x)[t];
                    v = fmaf(ryB, w384s[k0 + kk], v);
                    v = fmaf(rxB, w385s[k0 + kk], v);
                    As[kk * 132 + rB] = fmaxf(v, 0.f);
                }
            }
        }
        // stage W2 chunk with unit swizzle
#pragma unroll
        for (int i = 0; i < 4; i++) {
            int e = tid + 256 * i;
            int kk = e >> 5, u = e & 31;
            *(float4*)&Bs[kk * 128 + swz(u) * 4] =
                *(const float4*)&W2[(k0 + kk) * 128 + u * 4];
        }
        // prefetch next g_h1f half-chunk
        if (k0 < 224 && nbB >= 0) {
            const float* fr = g_h1f + nbB * 256 + k0 + 32 + khB * 16;
#pragma unroll
            for (int j = 0; j < 4; j++) pf[j] = *(const float4*)&fr[j * 4];
        }
        __syncthreads();                  // As/Bs visible
#pragma unroll
        for (int kk = 0; kk < 32; kk++) {
            ulonglong2 aA = *(const ulonglong2*)&As[kk * 132 + ty * 8];
            ulonglong2 aB = *(const ulonglong2*)&As[kk * 132 + ty * 8 + 4];
            ull a_pk[4] = {aA.x, aA.y, aB.x, aB.y};
            float4 bv0 = *(const float4*)&Bs[kk * 128 + ub0 * 4];
            float4 bv1 = *(const float4*)&Bs[kk * 128 + ub1 * 4];
            ull b_pk[8];
            b_pk[0] = pack2(bv0.x, bv0.x); b_pk[1] = pack2(bv0.y, bv0.y);
            b_pk[2] = pack2(bv0.z, bv0.z); b_pk[3] = pack2(bv0.w, bv0.w);
            b_pk[4] = pack2(bv1.x, bv1.x); b_pk[5] = pack2(bv1.y, bv1.y);
            b_pk[6] = pack2(bv1.z, bv1.z); b_pk[7] = pack2(bv1.w, bv1.w);
#pragma unroll
            for (int i = 0; i < 4; i++)
#pragma unroll
                for (int j = 0; j < 8; j++)
                    acc[i][j] = fma2(a_pk[i], b_pk[j], acc[i][j]);
        }
    }
    __syncthreads();                      // layer2 done; phase A smem free

    // relu(l2 + b2) -> A3 transposed [k2][r], 16B units swizzled by (k2>>3)&7
#pragma unroll
    for (int j = 0; j < 8; j++) {
        int k2 = tx * 8 + j;
        int sw = (k2 >> 3) & 7;
        float bb = b2s[k2];
#pragma unroll
        for (int i2 = 0; i2 < 4; i2++) {
            float2 u = unpack2(acc[i2][j]);
            float2 o;
            o.x = fmaxf(u.x + bb, 0.f);
            o.y = fmaxf(u.y + bb, 0.f);
            int ro = ty * 8 + 2 * i2;            // row offset within 128
            int ur = (ro >> 2) ^ sw;             // swizzled 16B unit
            int intra = ro & 3;
            *(float2*)&A3[k2 * 132 + ur * 4 + intra] = o;
        }
    }
    __syncthreads();

    // ---- layer 3: C3[128,32] = A3^T @ W3, k-split GEMM ----
    {
        const int kh = tid >> 7;          // k-half
        const int rem = tid & 127;
        const int rg = rem >> 3;          // rows rg*8..+7
        const int cg = rem & 7;           // cols cg*4..+3
        ull a3[4][4];
#pragma unroll
        for (int p = 0; p < 4; p++)
#pragma unroll
            for (int j = 0; j < 4; j++) a3[p][j] = pack2(0.f, 0.f);

        const float* w_base = W3s + (uint32_t)kh * 64 * 32 + cg * 4;
        for (int kt = 0; kt < 64; kt++) {
            int k2 = kh * 64 + kt;
            int sw = (k2 >> 3) & 7;
            const float* arow = A3 + k2 * 132;
            ulonglong2 aA = *(const ulonglong2*)&arow[((2 * rg) ^ sw) * 4];
            ulonglong2 aB = *(const ulonglong2*)&arow[((2 * rg + 1) ^ sw) * 4];
            float4 wv = *(const float4*)(w_base + kt * 32);
            ull w0 = pack2(wv.x, wv.x), w1 = pack2(wv.y, wv.y);
            ull w2 = pack2(wv.z, wv.z), w3v = pack2(wv.w, wv.w);
            ull ap[4] = {aA.x, aA.y, aB.x, aB.y};
#pragma unroll
            for (int p = 0; p < 4; p++) {
                a3[p][0] = fma2(ap[p], w0, a3[p][0]);
                a3[p][1] = fma2(ap[p], w1, a3[p][1]);
                a3[p][2] = fma2(ap[p], w2, a3[p][2]);
                a3[p][3] = fma2(ap[p], w3v, a3[p][3]);
            }
        }
        if (kh == 1) {
#pragma unroll
            for (int p = 0; p < 4; p++)
#pragma unroll
                for (int j = 0; j < 4; j++) {
                    float2 u = unpack2(a3[p][j]);
                    C3s[(rg * 8 + 2 * p) * 33 + cg * 4 + j]     = u.x;
                    C3s[(rg * 8 + 2 * p + 1) * 33 + cg * 4 + j] = u.y;
                }
        }
        __syncthreads();
        if (kh == 0) {
#pragma unroll
            for (int p = 0; p < 4; p++)
#pragma unroll
                for (int j = 0; j < 4; j++) {
                    float2 u = unpack2(a3[p][j]);
                    C3s[(rg * 8 + 2 * p) * 33 + cg * 4 + j]     += u.x;
                    C3s[(rg * 8 + 2 * p + 1) * 33 + cg * 4 + j] += u.y;
                }
        }
        __syncthreads();
    }

    // ---- softmax blend + coalesced channel-major store ----
#pragma unroll
    for (int i = 0; i < 4; i++) {
        int idx = tid + 256 * i;
        int pt = idx & 31, n = idx >> 5;
        float s = b3s[n];                 // sum(w)=1 -> bias post-blend
#pragma unroll
        for (int q = 0; q < 4; q++)
            s = fmaf(wq[pt * 4 + q], C3s[(pt * 4 + q) * 33 + n], s);
        out[n * NPTS + p0 + pt] = s;
    }
}

// ---------------------------------------------------------------------------
extern "C" void kernel_launch(void* const* d_in, const int* in_sizes, int n_in,
                              void* d_out, int out_size)
{
    const float* feat     = (const float*)d_in[0];
    const float* lr_guide = (const float*)d_in[1];
    const float* hr_guide = (const float*)d_in[2];
    const float* W1       = (const float*)d_in[3];
    const float* b1       = (const float*)d_in[4];
    const float* W2       = (const float*)d_in[5];
    const float* b2       = (const float*)d_in[6];
    const float* W3       = (const float*)d_in[7];
    const float* b3       = (const float*)d_in[8];
    float* out = (float*)d_out;

    void* h1f_p = nullptr;
    void* h1g_p = nullptr;
    cudaGetSymbolAddress(&h1f_p, g_h1f);
    cudaGetSymbolAddress(&h1g_p, g_h1g);

    // merged layer-1 GEMMs: 256 K1-blocks + 1024 K2-blocks
    gemm_l1_merged<<<1280, 256>>>(lr_guide, feat, hr_guide, W1, b1,
                                  (float*)h1f_p, (float*)h1g_p);

    // fused tail
    {
        cudaFuncSetAttribute(fused_tail, cudaFuncAttributeMaxDynamicSharedMemorySize,
                             TAIL_SMEM_BYTES);
        fused_tail<<<NPTS / 32, 256, TAIL_SMEM_BYTES>>>(
            feat, W1, W2, b2, W3, b3, out);
    }
}